// round 4
// baseline (speedup 1.0000x reference)
#include <cuda_runtime.h>

#define D      1024
#define PD     32
#define NPAT   256
#define TOPK   4
#define THREADS 256

__global__ __launch_bounds__(THREADS) void peer_fused_kernel(
    const float* __restrict__ x,
    const float* __restrict__ hw,      // [PD, D]
    const float* __restrict__ keys,    // [NPAT, PD]
    const float* __restrict__ vd,      // [NPAT, D, PD]
    const float* __restrict__ vu,      // [NPAT, PD, D]
    const float* __restrict__ scale,   // [1]
    float* __restrict__ out)
{
    __shared__ float xs[D];
    __shared__ float hs[PD];
    __shared__ float sims[NPAT];
    __shared__ float partial[8 * 32];   // [warp][j]
    __shared__ float proj[PD];
    __shared__ float wk_s[TOPK];
    __shared__ int   idx_s[TOPK];
    __shared__ float kval_s[TOPK];
    __shared__ float scale_s;

    const int tok  = blockIdx.x;
    const int tid  = threadIdx.x;
    const int lane = tid & 31;
    const int w    = tid >> 5;

    // ---- stage x into smem (coalesced float4) ----
    const float4* xg4 = reinterpret_cast<const float4*>(x + (size_t)tok * D);
    float4 xv4 = xg4[tid];
    reinterpret_cast<float4*>(xs)[tid] = xv4;
    if (tid == 0) scale_s = scale[0];
    __syncthreads();

    // ---- hash: h[j] = dot(hw[j], x). warp w owns j = 4w..4w+3 (coalesced hw rows)
    {
        const float4* hw4 = reinterpret_cast<const float4*>(hw);
        const float4* xs4 = reinterpret_cast<const float4*>(xs);
        #pragma unroll
        for (int jj = 0; jj < 4; jj++) {
            const int j = w * 4 + jj;
            float acc = 0.f;
            #pragma unroll
            for (int i = 0; i < 8; i++) {
                float4 a = hw4[j * (D / 4) + lane + 32 * i];
                float4 b = xs4[lane + 32 * i];
                acc += a.x * b.x + a.y * b.y + a.z * b.z + a.w * b.w;
            }
            #pragma unroll
            for (int off = 16; off; off >>= 1)
                acc += __shfl_xor_sync(0xFFFFFFFFu, acc, off);
            if (lane == 0) hs[j] = acc;
        }
    }
    __syncthreads();

    // ---- sim[n] = dot(keys[n], h): one pattern per thread ----
    {
        const float4* k4 = reinterpret_cast<const float4*>(keys + tid * PD);
        const float4* h4 = reinterpret_cast<const float4*>(hs);
        float s = 0.f;
        #pragma unroll
        for (int i = 0; i < 8; i++) {
            float4 a = k4[i]; float4 b = h4[i];
            s += a.x * b.x + a.y * b.y + a.z * b.z + a.w * b.w;
        }
        sims[tid] = s;
    }
    __syncthreads();

    // ---- top-4 (warp 0), ties -> lower index (matches lax.top_k) ----
    if (w == 0) {
        for (int k = 0; k < TOPK; k++) {
            float bv = -1e30f; int bi = 0;
            #pragma unroll
            for (int t = 0; t < 8; t++) {
                const int n = lane * 8 + t;
                const float v = sims[n];
                if (v > bv) { bv = v; bi = n; }
            }
            #pragma unroll
            for (int off = 16; off; off >>= 1) {
                const float ov = __shfl_xor_sync(0xFFFFFFFFu, bv, off);
                const int   oi = __shfl_xor_sync(0xFFFFFFFFu, bi, off);
                if (ov > bv || (ov == bv && oi < bi)) { bv = ov; bi = oi; }
            }
            if (lane == 0) { idx_s[k] = bi; kval_s[k] = bv; sims[bi] = -1e30f; }
            __syncwarp();
        }
        if (lane == 0) {
            const float m = kval_s[0];           // pass 0 found the max
            float e[TOPK]; float ssum = 0.f;
            #pragma unroll
            for (int k = 0; k < TOPK; k++) { e[k] = expf(kval_s[k] - m); ssum += e[k]; }
            const float sc = scale_s / ssum;     // fold scale into the softmax weight
            #pragma unroll
            for (int k = 0; k < TOPK; k++) wk_s[k] = e[k] * sc;
        }
    }
    __syncthreads();

    // ---- expert loop: down-proj -> silu -> up-proj, w_k*scale folded into proj
    float4 oacc = make_float4(0.f, 0.f, 0.f, 0.f);
    const int jq   = lane & 7;   // j-quad (4 consecutive j per float4)
    const int dsub = lane >> 3;  // 4 d-subgroups per warp

    for (int k = 0; k < TOPK; k++) {
        const int p = idx_s[k];
        const float4* vd4 = reinterpret_cast<const float4*>(vd + (size_t)p * D * PD);

        // down: proj[j] = sum_d x[d] * vd[d][j]; warp reads 4 full 128B rows per request
        float4 acc = make_float4(0.f, 0.f, 0.f, 0.f);
        const int dbase = w * 128 + dsub * 32;
        #pragma unroll
        for (int i = 0; i < 32; i++) {
            const int d = dbase + i;
            const float xv = xs[d];
            const float4 r = vd4[d * (PD / 4) + jq];
            acc.x += xv * r.x; acc.y += xv * r.y;
            acc.z += xv * r.z; acc.w += xv * r.w;
        }
        // reduce over dsub within the warp (xor 8, 16)
        #pragma unroll
        for (int off = 8; off < 32; off <<= 1) {
            acc.x += __shfl_xor_sync(0xFFFFFFFFu, acc.x, off);
            acc.y += __shfl_xor_sync(0xFFFFFFFFu, acc.y, off);
            acc.z += __shfl_xor_sync(0xFFFFFFFFu, acc.z, off);
            acc.w += __shfl_xor_sync(0xFFFFFFFFu, acc.w, off);
        }
        if (dsub == 0)
            reinterpret_cast<float4*>(partial)[w * 8 + jq] = acc;
        __syncthreads();

        if (tid < PD) {
            float s = 0.f;
            #pragma unroll
            for (int ww = 0; ww < 8; ww++) s += partial[ww * 32 + tid];
            const float sig = 1.f / (1.f + expf(-s));
            proj[tid] = s * sig * wk_s[k];       // silu(s) * w_k * scale
        }
        __syncthreads();

        // up: oacc[d] += proj[j] * vu[j][d]; perfectly coalesced float4
        const float4* vu4 = reinterpret_cast<const float4*>(vu + (size_t)p * PD * D);
        #pragma unroll
        for (int j = 0; j < PD; j++) {
            const float pj = proj[j];            // smem broadcast
            const float4 r = vu4[j * (D / 4) + tid];
            oacc.x += pj * r.x; oacc.y += pj * r.y;
            oacc.z += pj * r.z; oacc.w += pj * r.w;
        }
        // no trailing sync needed: next iter's proj write is gated by the
        // post-partial __syncthreads, which no thread reaches before finishing
        // its up-phase reads of proj.
    }

    float4 res;
    res.x = xv4.x + oacc.x; res.y = xv4.y + oacc.y;
    res.z = xv4.z + oacc.z; res.w = xv4.w + oacc.w;
    reinterpret_cast<float4*>(out)[(size_t)tok * (D / 4) + tid] = res;
}

extern "C" void kernel_launch(void* const* d_in, const int* in_sizes, int n_in,
                              void* d_out, int out_size) {
    const float* x     = (const float*)d_in[0];
    const float* hw    = (const float*)d_in[1];
    const float* keys  = (const float*)d_in[2];
    const float* vd    = (const float*)d_in[3];
    const float* vu    = (const float*)d_in[4];
    const float* scale = (const float*)d_in[5];
    float* out = (float*)d_out;

    const int ntok = in_sizes[0] / D;   // B*T = 2048
    peer_fused_kernel<<<ntok, THREADS>>>(x, hw, keys, vd, vu, scale, out);
}